// round 9
// baseline (speedup 1.0000x reference)
#include <cuda_runtime.h>
#include <stdint.h>

// ---------------------------------------------------------------------------
// LogSqrt2Quantizer — single persistent fused kernel (round-7 exact source,
// the measured-fastest hot path: kernel 120.2us, DRAM 79.3%).
//
// Math collapse: the reference chain depends on x only through
//   mp = round(log2(v)),  v = rint(x / s_x) + bias  (exact integer in
//   [66, 65602]).
// Each persistent block builds the 32-entry mp -> out table once in shared
// memory with IEEE-exact fp32 ops (__fdiv_rn / rintf; rel_err == 0.0
// verified rounds 3 and 5-8).
//
// mp bit trick: vf = rint(x * 2^16) + 66 is an exact fp32 integer, so its
// bits are ((n+127)<<23) | m with n = floor(log2 v). round(log2 v) = n +
// (m >= ceil(frac(sqrt2) * 2^23) = 3474676); the sqrt(2) mantissa threshold
// is exponent-independent and ties are impossible. Adding
// K = 2^23 - 3474676 = 4913932 carries that test into the exponent field:
//     mp + 127 = (float_as_int(vf) + 4913932) >> 23
// (bit-equivalent to the verified v*v >= 2^(2n+1) integer test).
//
// Lessons locked in:
//  - R6/R8: ANY front-batched multi-stream unroll reduces DRAM active %
//    (more concurrent address streams -> worse DRAM page/LTS locality).
//    Plain grid-stride = one contiguous chip-wide window. Keep it.
//  - R6: occupancy must stay at 8 CTA/SM.
//  - DRAM ~79% is the effective ceiling for this balanced r/w stream.
// ---------------------------------------------------------------------------

__device__ __forceinline__ int lsq_idx(float x, float inv_sx, float biasf) {
    float vf = rintf(x * inv_sx) + biasf;          // exact integer in fp32
    return (__float_as_int(vf) + 4913932) >> 23;   // = mp + 127
}

__global__ void __launch_bounds__(256, 8)
lsq_fused_kernel(const float4* __restrict__ in, float4* __restrict__ out,
                 const float* __restrict__ s_x_p,
                 const float* __restrict__ bias_p,
                 const float* __restrict__ minv_p,
                 const float* __restrict__ maxv_p,
                 const float* __restrict__ lut,
                 int n4, int n, int out_size) {
    __shared__ float s_tab[32];
    __shared__ float s_inv_sx;
    __shared__ float s_biasf;

    const unsigned tid = threadIdx.x;

    // --- per-block prologue (once per persistent block, ~1.2K total) ------
    if (tid < 32) {
        const float sx = __ldg(s_x_p);
        const float mn = __ldg(minv_p);
        const float mx = __ldg(maxv_p);
        const float c  = 40342.0f;                       // rint(2^15.3)
        const float scale = __fdiv_rn(mx - mn, 15.0f);
        const float zp    = rintf(__fdiv_rn(-mn, scale));
        float y  = (float)(-(int)tid) * c;
        float qf = rintf(__fdiv_rn(y, scale)) + zp;
        qf = fminf(fmaxf(qf, 0.0f), 15.0f);
        s_tab[tid] = __ldg(&lut[(int)qf]) * sx;
        if (tid == 0) {
            s_inv_sx = __fdiv_rn(1.0f, sx);    // exact: s_x is a power of two
            s_biasf  = __ldg(bias_p);          // 66.0f (exact small integer)
        }
    } else if (tid < 64 && blockIdx.x == 0) {
        // Tuple tail: out[n .. out_size) = s_x (usually a single element).
        const float sx = __ldg(s_x_p);
        float* out_f = (float*)out;
        for (int j = n + (int)(tid - 32); j < out_size; j += 32)
            out_f[j] = sx;
    }
    __syncthreads();

    const float inv_sx = s_inv_sx;
    const float biasf  = s_biasf;
    const float* tabm = s_tab - 127;           // rebase: index is mp+127

    // --- persistent grid-stride stream (single contiguous window) ---------
    const int stride = gridDim.x * blockDim.x;
    for (int i = blockIdx.x * blockDim.x + tid; i < n4; i += stride) {
        float4 x = __ldcs(&in[i]);             // evict-first: pure stream
        float4 r;
        r.x = tabm[lsq_idx(x.x, inv_sx, biasf)];
        r.y = tabm[lsq_idx(x.y, inv_sx, biasf)];
        r.z = tabm[lsq_idx(x.z, inv_sx, biasf)];
        r.w = tabm[lsq_idx(x.w, inv_sx, biasf)];
        __stcs(&out[i], r);
    }
}

extern "C" void kernel_launch(void* const* d_in, const int* in_sizes, int n_in,
                              void* d_out, int out_size) {
    const float* x_hat = (const float*)d_in[0];
    const float* s_x   = (const float*)d_in[1];
    const float* bias  = (const float*)d_in[2];
    const float* minv  = (const float*)d_in[3];
    const float* maxv  = (const float*)d_in[4];
    const float* lut   = (const float*)d_in[5];
    float* out = (float*)d_out;

    const int n  = in_sizes[0];
    const int n4 = n >> 2;                     // N divisible by 4

    // Persistent launch: 8 CTAs per SM on GB300's 152 SMs.
    const int threads = 256;
    int blocks = 152 * 8;
    const int max_blocks = (n4 + threads - 1) / threads;
    if (blocks > max_blocks) blocks = max_blocks;

    lsq_fused_kernel<<<blocks, threads>>>((const float4*)x_hat, (float4*)out,
                                          s_x, bias, minv, maxv, lut,
                                          n4, n, out_size);
}